// round 3
// baseline (speedup 1.0000x reference)
#include <cuda_runtime.h>
#include <math.h>

// Problem constants (fixed benchmark shapes)
#define N_PTS   50000
#define C_FEAT  128
#define HF      480
#define WF      640
#define IMW     640
#define IMH     480
#define HW      (HF*WF)
#define NITERS  10

#define GH_BLOCKS   592
#define GH_THREADS  256
#define COST_BLOCKS 592
#define COST_THREADS 256

// ---------------- persistent device state ----------------
// Packed pixel-major maps: per pixel 96 float4 = [fm(32 f4) | gx(32 f4) | gy(32 f4)]
__device__ float4 g_packed[(size_t)HW * 96];

__device__ float  g_R[9], g_t[3], g_Rc[9], g_tc[3];
__device__ float  g_lam, g_lr;
__device__ double g_prev_cost;
__device__ double g_gh[GH_BLOCKS][27];
__device__ double g_cost[COST_BLOCKS][2];

// Hessian upper-triangle index maps (21 entries)
__device__ const int c_hk[21] = {0,0,0,0,0,0,1,1,1,1,1,2,2,2,2,3,3,3,4,4,5};
__device__ const int c_hl[21] = {0,1,2,3,4,5,1,2,3,4,5,2,3,4,5,3,4,5,4,5,5};

// ---------------- init ----------------
__global__ void init_kernel(const float* __restrict__ R0, const float* __restrict__ t0) {
    int t = threadIdx.x;
    if (t < 9) g_R[t] = R0[t];
    if (t < 3) g_t[t] = t0[t];
    if (t == 0) { g_lam = 0.01f; g_lr = 1.0f; }
}

// ---------------- transpose (C,H,W) x3 -> (pix, map, C) ----------------
__global__ __launch_bounds__(256) void transpose_kernel(
    const float* __restrict__ fm, const float* __restrict__ gx, const float* __restrict__ gy)
{
    __shared__ float sh[32][C_FEAT + 1];
    int b    = blockIdx.x;            // (HW/32)*3 blocks
    int map  = b / (HW / 32);
    int tile = b % (HW / 32);
    int pix0 = tile * 32;
    const float* src = (map == 0) ? fm : (map == 1) ? gx : gy;

    int t = threadIdx.x, lane = t & 31, grp = t >> 5;   // 8 groups
    #pragma unroll
    for (int cb = 0; cb < C_FEAT; cb += 8) {
        int ch = cb + grp;
        sh[lane][ch] = src[(size_t)ch * HW + pix0 + lane];
    }
    __syncthreads();
    float* out = (float*)g_packed;
    #pragma unroll
    for (int pb = 0; pb < 32; pb += 8) {
        int p = pb + grp;
        size_t base = (size_t)(pix0 + p) * 384 + (size_t)map * 128;
        #pragma unroll
        for (int k = 0; k < 4; k++)
            out[base + k * 32 + lane] = sh[p][k * 32 + lane];
    }
}

// ---------------- projection helper ----------------
__device__ __forceinline__ bool project_pt(
    float X0, float Y0, float Z0,
    const float* R, const float* t,
    float fx, float fy, float cx, float cy,
    float& X, float& Y, float& Z, int& px, int& py)
{
    X = R[0]*X0 + R[1]*Y0 + R[2]*Z0 + t[0];
    Y = R[3]*X0 + R[4]*Y0 + R[5]*Z0 + t[1];
    Z = R[6]*X0 + R[7]*Y0 + R[8]*Z0 + t[2];
    float u = (fx*X + cx*Z) / Z;
    float v = (fy*Y + cy*Z) / Z;
    u = fminf(fmaxf(u, -1e6f), 1e6f);
    v = fminf(fmaxf(v, -1e6f), 1e6f);
    px = (int)rintf(u) - 1;
    py = (int)rintf(v) - 1;
    return (px >= 0) && (py >= 0) && (px < IMW) && (py < IMH);
}

// ---------------- gradient + Hessian reduction ----------------
__global__ __launch_bounds__(GH_THREADS) void gradhess_kernel(
    const float* __restrict__ pts, const float* __restrict__ fref,
    const float* __restrict__ Kmat)
{
    const float fx = Kmat[0], cx = Kmat[2], fy = Kmat[4], cy = Kmat[5];
    const int lane = threadIdx.x & 31;
    const int wid  = (blockIdx.x * blockDim.x + threadIdx.x) >> 5;
    const int nw   = (GH_BLOCKS * GH_THREADS) >> 5;

    int kk = 0, ll = 0;
    if (lane >= 6 && lane < 27) { kk = c_hk[lane - 6]; ll = c_hl[lane - 6]; }

    float Rl[9], tl[3];
    #pragma unroll
    for (int i = 0; i < 9; i++) Rl[i] = g_R[i];
    #pragma unroll
    for (int i = 0; i < 3; i++) tl[i] = g_t[i];

    const float4* frf4 = (const float4*)fref;
    double acc = 0.0;

    for (int i = wid; i < N_PTS; i += nw) {
        float X0 = pts[3*i], Y0 = pts[3*i+1], Z0 = pts[3*i+2];
        float X, Y, Z; int px, py;
        bool in = project_pt(X0, Y0, Z0, Rl, tl, fx, fy, cx, cy, X, Y, Z, px, py);
        if (!in) continue;   // warp-uniform

        int r = py, c = px;  // in-bounds => clip is identity (Hf==H, Wf==W)
        const float4* pb = g_packed + (size_t)(r * WF + c) * 96;
        float4 f  = pb[lane];
        float4 a  = pb[32 + lane];
        float4 bb = pb[64 + lane];
        float4 fr = frf4[(size_t)i * 32 + lane];

        float ex = f.x - fr.x, ey = f.y - fr.y, ez = f.z - fr.z, ew = f.w - fr.w;
        float sxx = a.x*a.x + a.y*a.y + a.z*a.z + a.w*a.w;
        float syy = bb.x*bb.x + bb.y*bb.y + bb.z*bb.z + bb.w*bb.w;
        float sxy = a.x*bb.x + a.y*bb.y + a.z*bb.z + a.w*bb.w;
        float sxe = a.x*ex + a.y*ey + a.z*ez + a.w*ew;
        float sye = bb.x*ex + bb.y*ey + bb.z*ez + bb.w*ew;
        #pragma unroll
        for (int o = 16; o; o >>= 1) {
            sxx += __shfl_xor_sync(0xffffffffu, sxx, o);
            syy += __shfl_xor_sync(0xffffffffu, syy, o);
            sxy += __shfl_xor_sync(0xffffffffu, sxy, o);
            sxe += __shfl_xor_sync(0xffffffffu, sxe, o);
            sye += __shfl_xor_sync(0xffffffffu, sye, o);
        }

        float Zs  = (fabsf(Z) > 1e-6f) ? Z : 1e-6f;
        float iz  = 1.0f / Zs;
        float iz2 = iz * iz;
        float A00 =  fx * iz,            A01 = 0.0f,               A02 = -fx * X * iz2;
        float A03 = -fx * X * Y * iz2,   A04 = fx*Z*iz + fx*X*X*iz2, A05 = -fx * Y * iz;
        float A10 = 0.0f,                A11 = fy * iz,            A12 = -fy * Y * iz2;
        float A13 = -fy*Z*iz - fy*Y*Y*iz2, A14 = fy * X * Y * iz2, A15 =  fy * X * iz;

        float a0 = (lane==0)?A00:(lane==1)?A01:(lane==2)?A02:(lane==3)?A03:(lane==4)?A04:A05;
        float a1 = (lane==0)?A10:(lane==1)?A11:(lane==2)?A12:(lane==3)?A13:(lane==4)?A14:A15;
        float A0k = __shfl_sync(0xffffffffu, a0, kk);
        float A0l = __shfl_sync(0xffffffffu, a0, ll);
        float A1k = __shfl_sync(0xffffffffu, a1, kk);
        float A1l = __shfl_sync(0xffffffffu, a1, ll);

        float term;
        if (lane < 6) term = sxe * a0 + sye * a1;
        else          term = sxx*A0k*A0l + sxy*(A0k*A1l + A1k*A0l) + syy*A1k*A1l;
        if (lane < 27) acc += (double)term;
    }

    __shared__ double sred[GH_THREADS/32][27];
    int w = threadIdx.x >> 5;
    if (lane < 27) sred[w][lane] = acc;
    __syncthreads();
    if (threadIdx.x < 27) {
        double s = 0.0;
        #pragma unroll
        for (int j = 0; j < GH_THREADS/32; j++) s += sred[j][threadIdx.x];
        g_gh[blockIdx.x][threadIdx.x] = s;
    }
}

// ---------------- masked cost reduction ----------------
__global__ __launch_bounds__(COST_THREADS) void cost_kernel(
    const float* __restrict__ pts, const float* __restrict__ fref,
    const float* __restrict__ Kmat, int use_cand)
{
    const float fx = Kmat[0], cx = Kmat[2], fy = Kmat[4], cy = Kmat[5];
    const int lane = threadIdx.x & 31;
    const int wid  = (blockIdx.x * blockDim.x + threadIdx.x) >> 5;
    const int nw   = (COST_BLOCKS * COST_THREADS) >> 5;

    float Rl[9], tl[3];
    const float* Rs = use_cand ? g_Rc : g_R;
    const float* ts = use_cand ? g_tc : g_t;
    #pragma unroll
    for (int i = 0; i < 9; i++) Rl[i] = Rs[i];
    #pragma unroll
    for (int i = 0; i < 3; i++) tl[i] = ts[i];

    const float4* frf4 = (const float4*)fref;
    double acc = 0.0;
    double cnt = 0.0;

    for (int i = wid; i < N_PTS; i += nw) {
        float X0 = pts[3*i], Y0 = pts[3*i+1], Z0 = pts[3*i+2];
        float X, Y, Z; int px, py;
        bool in = project_pt(X0, Y0, Z0, Rl, tl, fx, fy, cx, cy, X, Y, Z, px, py);
        if (!in) continue;   // warp-uniform

        const float4* pb = g_packed + (size_t)(py * WF + px) * 96;
        float4 f  = pb[lane];
        float4 fr = frf4[(size_t)i * 32 + lane];
        float ex = f.x - fr.x, ey = f.y - fr.y, ez = f.z - fr.z, ew = f.w - fr.w;
        float e2 = ex*ex + ey*ey + ez*ez + ew*ew;
        acc += (double)e2;            // per-lane partial; reduced once at end
        if (lane == 0) cnt += 1.0;
    }

    // warp reduce
    #pragma unroll
    for (int o = 16; o; o >>= 1) {
        acc += __shfl_xor_sync(0xffffffffu, acc, o);
        cnt += __shfl_xor_sync(0xffffffffu, cnt, o);
    }
    __shared__ double s2[COST_THREADS/32][2];
    int w = threadIdx.x >> 5;
    if (lane == 0) { s2[w][0] = acc; s2[w][1] = cnt; }
    __syncthreads();
    if (threadIdx.x == 0) {
        double sa = 0.0, sc = 0.0;
        #pragma unroll
        for (int j = 0; j < COST_THREADS/32; j++) { sa += s2[j][0]; sc += s2[j][1]; }
        g_cost[blockIdx.x][0] = 0.5 * sa;
        g_cost[blockIdx.x][1] = sc;
    }
}

// ---------------- 6x6 LM solve + pose composition ----------------
__global__ void solve_kernel() {
    __shared__ double red[27];
    int t = threadIdx.x;
    if (t < 27) {
        double s = 0.0;
        for (int b = 0; b < GH_BLOCKS; b++) s += g_gh[b][t];
        red[t] = s;
    }
    __syncthreads();
    if (t != 0) return;

    double G[6];
    #pragma unroll
    for (int j = 0; j < 6; j++) G[j] = red[j];
    double H[6][6];
    {
        int idx = 6;
        for (int k = 0; k < 6; k++)
            for (int l = k; l < 6; l++) { H[k][l] = red[idx]; H[l][k] = red[idx]; idx++; }
    }
    double lam = (double)g_lam;
    for (int k = 0; k < 6; k++) H[k][k] += lam * (H[k][k] + 1e-9);

    // Gaussian elimination with partial pivoting: H x = G
    double M[6][7];
    for (int k = 0; k < 6; k++) { for (int j = 0; j < 6; j++) M[k][j] = H[k][j]; M[k][6] = G[k]; }
    for (int k = 0; k < 6; k++) {
        int p = k; double mx = fabs(M[k][k]);
        for (int r = k + 1; r < 6; r++) if (fabs(M[r][k]) > mx) { mx = fabs(M[r][k]); p = r; }
        if (p != k) for (int j = k; j < 7; j++) { double tmp = M[k][j]; M[k][j] = M[p][j]; M[p][j] = tmp; }
        double inv = 1.0 / M[k][k];
        for (int j = k; j < 7; j++) M[k][j] *= inv;
        for (int r = 0; r < 6; r++) if (r != k) {
            double f = M[r][k];
            for (int j = k; j < 7; j++) M[r][j] -= f * M[k][j];
        }
    }
    double lr = (double)g_lr;
    double dt0 = -lr * M[0][6], dt1 = -lr * M[1][6], dt2 = -lr * M[2][6];
    double w0  = -lr * M[3][6], w1  = -lr * M[4][6], w2  = -lr * M[5][6];

    // so3exp
    double th2 = w0*w0 + w1*w1 + w2*w2;
    double th  = sqrt(th2 + 1e-24);
    double a, b;
    if (th < 1e-4) { a = 1.0 - th2 / 6.0; b = 0.5 - th2 / 24.0; }
    else           { a = sin(th) / th;    b = (1.0 - cos(th)) / (th2 + 1e-24); }
    double W[9]  = {0, -w2, w1,  w2, 0, -w0,  -w1, w0, 0};
    double W2[9];
    for (int r = 0; r < 3; r++)
        for (int c = 0; c < 3; c++) {
            double s = 0;
            for (int k = 0; k < 3; k++) s += W[r*3+k] * W[k*3+c];
            W2[r*3+c] = s;
        }
    double dr[9];
    for (int i = 0; i < 9; i++) dr[i] = a * W[i] + b * W2[i];
    dr[0] += 1.0; dr[4] += 1.0; dr[8] += 1.0;

    double Rc[9], tc[3];
    double Rcur[9], tcur[3];
    for (int i = 0; i < 9; i++) Rcur[i] = (double)g_R[i];
    for (int i = 0; i < 3; i++) tcur[i] = (double)g_t[i];
    for (int r = 0; r < 3; r++)
        for (int c = 0; c < 3; c++) {
            double s = 0;
            for (int k = 0; k < 3; k++) s += dr[r*3+k] * Rcur[k*3+c];
            Rc[r*3+c] = s;
        }
    for (int r = 0; r < 3; r++) {
        double s = 0;
        for (int k = 0; k < 3; k++) s += dr[r*3+k] * tcur[k];
        tc[r] = s;
    }
    tc[0] += dt0; tc[1] += dt1; tc[2] += dt2;

    for (int i = 0; i < 9; i++) g_Rc[i] = (float)Rc[i];
    for (int i = 0; i < 3; i++) g_tc[i] = (float)tc[i];
}

// ---------------- accept / init-cost ----------------
__global__ void accept_kernel(int is_init) {
    int t = threadIdx.x;
    double s = 0.0, c = 0.0;
    for (int b = t; b < COST_BLOCKS; b += 32) { s += g_cost[b][0]; c += g_cost[b][1]; }
    #pragma unroll
    for (int o = 16; o; o >>= 1) {
        s += __shfl_xor_sync(0xffffffffu, s, o);
        c += __shfl_xor_sync(0xffffffffu, c, o);
    }
    if (t != 0) return;
    double cost = s / fmax(c, 1.0);
    if (is_init) { g_prev_cost = cost; return; }

    bool accept = (cost <= g_prev_cost);
    float lam = g_lam * (accept ? 0.1f : 10.0f);
    g_lam = fminf(fmaxf(lam, 1e-6f), 1e4f);
    g_lr  = accept ? 1.0f : fminf(fmaxf(0.1f * g_lr, 1e-3f), 1.0f);
    if (accept) {
        for (int i = 0; i < 9; i++) g_R[i] = g_Rc[i];
        for (int i = 0; i < 3; i++) g_t[i] = g_tc[i];
        g_prev_cost = cost;
    }
}

// ---------------- write output ----------------
__global__ void writeout_kernel(float* out) {
    int t = threadIdx.x;
    if (t < 9) out[t]     = g_R[t];
    if (t < 3) out[9 + t] = g_t[t];
}

// ---------------- launch ----------------
extern "C" void kernel_launch(void* const* d_in, const int* in_sizes, int n_in,
                              void* d_out, int out_size)
{
    const float* pts  = (const float*)d_in[0];   // pts3D (N,3)
    const float* fref = (const float*)d_in[1];   // feature_ref (N,C)
    const float* fm   = (const float*)d_in[2];   // feature_map_query (C,H,W)
    const float* gx   = (const float*)d_in[3];   // feature_grad_x
    const float* gy   = (const float*)d_in[4];   // feature_grad_y
    const float* Km   = (const float*)d_in[5];   // K (3,3)
    const float* R0   = (const float*)d_in[6];   // R_init
    const float* t0   = (const float*)d_in[7];   // t_init
    // d_in[8], d_in[9]: im_width/im_height (int scalars) — fixed to 640/480

    init_kernel<<<1, 32>>>(R0, t0);
    transpose_kernel<<<(HW / 32) * 3, 256>>>(fm, gx, gy);

    cost_kernel<<<COST_BLOCKS, COST_THREADS>>>(pts, fref, Km, 0);
    accept_kernel<<<1, 32>>>(1);

    for (int it = 0; it < NITERS; it++) {
        gradhess_kernel<<<GH_BLOCKS, GH_THREADS>>>(pts, fref, Km);
        solve_kernel<<<1, 32>>>();
        cost_kernel<<<COST_BLOCKS, COST_THREADS>>>(pts, fref, Km, 1);
        accept_kernel<<<1, 32>>>(0);
    }
    writeout_kernel<<<1, 32>>>((float*)d_out);
}

// round 4
// speedup vs baseline: 1.4507x; 1.4507x over previous
#include <cuda_runtime.h>
#include <math.h>

// Problem constants (fixed benchmark shapes)
#define N_PTS   50000
#define C_FEAT  128
#define HF      480
#define WF      640
#define IMW     640
#define IMH     480
#define HW      (HF*WF)
#define NITERS  10

#define MTHREADS 256
#define MAXB     1184

// ---------------- persistent device state ----------------
// Packed pixel-major maps: per pixel 96 float4 = [fm(32 f4) | gx(32 f4) | gy(32 f4)]
__device__ float4 g_packed[(size_t)HW * 96];

__device__ double   g_part[MAXB][29];   // per-block partials: 0..5 G, 6..26 H(ut), 27 sum(e2), 28 cnt
__device__ float    g_Rc[9], g_tc[3];   // candidate pose (block0 -> all blocks)
__device__ unsigned g_count = 0;        // barrier arrival counter (reset by releaser)
__device__ unsigned g_gen   = 0;        // barrier generation (monotonic)

// Hessian upper-triangle index maps (21 entries)
__device__ const int c_hk[21] = {0,0,0,0,0,0,1,1,1,1,1,2,2,2,2,3,3,3,4,4,5};
__device__ const int c_hl[21] = {0,1,2,3,4,5,1,2,3,4,5,2,3,4,5,3,4,5,4,5,5};

// ---------------- transpose (C,H,W) x3 -> (pix, map, C) ----------------
__global__ __launch_bounds__(256) void transpose_kernel(
    const float* __restrict__ fm, const float* __restrict__ gx, const float* __restrict__ gy)
{
    __shared__ float sh[32][C_FEAT + 1];
    int b    = blockIdx.x;            // (HW/32)*3 blocks
    int map  = b / (HW / 32);
    int tile = b % (HW / 32);
    int pix0 = tile * 32;
    const float* src = (map == 0) ? fm : (map == 1) ? gx : gy;

    int t = threadIdx.x, lane = t & 31, grp = t >> 5;   // 8 groups
    #pragma unroll
    for (int cb = 0; cb < C_FEAT; cb += 8) {
        int ch = cb + grp;
        sh[lane][ch] = src[(size_t)ch * HW + pix0 + lane];
    }
    __syncthreads();
    float* out = (float*)g_packed;
    #pragma unroll
    for (int pb = 0; pb < 32; pb += 8) {
        int p = pb + grp;
        size_t base = (size_t)(pix0 + p) * 384 + (size_t)map * 128;
        #pragma unroll
        for (int k = 0; k < 4; k++)
            out[base + k * 32 + lane] = sh[p][k * 32 + lane];
    }
}

// ---------------- software grid barrier (sense via monotonic generation) ----------------
__device__ __forceinline__ void gbar(int grid) {
    __syncthreads();
    if (threadIdx.x == 0) {
        unsigned gen = *(volatile unsigned*)&g_gen;   // read generation BEFORE arriving
        __threadfence();
        unsigned old = atomicAdd(&g_count, 1u);
        if (old == (unsigned)grid - 1u) {
            g_count = 0;                  // reset for next barrier
            __threadfence();
            atomicAdd(&g_gen, 1u);        // release
        } else {
            while (*(volatile unsigned*)&g_gen == gen) { }
        }
        __threadfence();
    }
    __syncthreads();
}

// ---------------- 6x6 LM solve + pose composition (block0 thread0 only) ----------------
__device__ __noinline__ void solve_compose(
    const double* __restrict__ GH, float lam_f, float lr_f,
    const float* __restrict__ Rcur, const float* __restrict__ tcur)
{
    double G[6];
    for (int j = 0; j < 6; j++) G[j] = GH[j];
    double H[6][6];
    {
        int idx = 6;
        for (int k = 0; k < 6; k++)
            for (int l = k; l < 6; l++) { H[k][l] = GH[idx]; H[l][k] = GH[idx]; idx++; }
    }
    double lam = (double)lam_f;
    for (int k = 0; k < 6; k++) H[k][k] += lam * (H[k][k] + 1e-9);

    // Gaussian elimination with partial pivoting: H x = G
    double M[6][7];
    for (int k = 0; k < 6; k++) { for (int j = 0; j < 6; j++) M[k][j] = H[k][j]; M[k][6] = G[k]; }
    for (int k = 0; k < 6; k++) {
        int p = k; double mx = fabs(M[k][k]);
        for (int r = k + 1; r < 6; r++) if (fabs(M[r][k]) > mx) { mx = fabs(M[r][k]); p = r; }
        if (p != k) for (int j = k; j < 7; j++) { double tmp = M[k][j]; M[k][j] = M[p][j]; M[p][j] = tmp; }
        double inv = 1.0 / M[k][k];
        for (int j = k; j < 7; j++) M[k][j] *= inv;
        for (int r = 0; r < 6; r++) if (r != k) {
            double f = M[r][k];
            for (int j = k; j < 7; j++) M[r][j] -= f * M[k][j];
        }
    }
    double lr = (double)lr_f;
    double dt0 = -lr * M[0][6], dt1 = -lr * M[1][6], dt2 = -lr * M[2][6];
    double w0  = -lr * M[3][6], w1  = -lr * M[4][6], w2  = -lr * M[5][6];

    // so3exp
    double th2 = w0*w0 + w1*w1 + w2*w2;
    double th  = sqrt(th2 + 1e-24);
    double a, b;
    if (th < 1e-4) { a = 1.0 - th2 / 6.0; b = 0.5 - th2 / 24.0; }
    else           { a = sin(th) / th;    b = (1.0 - cos(th)) / (th2 + 1e-24); }
    double W[9]  = {0, -w2, w1,  w2, 0, -w0,  -w1, w0, 0};
    double W2[9];
    for (int r = 0; r < 3; r++)
        for (int c = 0; c < 3; c++) {
            double s = 0;
            for (int k = 0; k < 3; k++) s += W[r*3+k] * W[k*3+c];
            W2[r*3+c] = s;
        }
    double dr[9];
    for (int i = 0; i < 9; i++) dr[i] = a * W[i] + b * W2[i];
    dr[0] += 1.0; dr[4] += 1.0; dr[8] += 1.0;

    double Rc[9], tc[3];
    for (int r = 0; r < 3; r++)
        for (int c = 0; c < 3; c++) {
            double s = 0;
            for (int k = 0; k < 3; k++) s += dr[r*3+k] * (double)Rcur[k*3+c];
            Rc[r*3+c] = s;
        }
    for (int r = 0; r < 3; r++) {
        double s = 0;
        for (int k = 0; k < 3; k++) s += dr[r*3+k] * (double)tcur[k];
        tc[r] = s;
    }
    tc[0] += dt0; tc[1] += dt1; tc[2] += dt2;

    for (int i = 0; i < 9; i++) g_Rc[i] = (float)Rc[i];
    for (int i = 0; i < 3; i++) g_tc[i] = (float)tc[i];
}

// ---------------- persistent mega-kernel ----------------
__global__ __launch_bounds__(MTHREADS, 3)
void mega_kernel(const float* __restrict__ pts, const float* __restrict__ fref,
                 const float* __restrict__ Kmat, const float* __restrict__ R0,
                 const float* __restrict__ t0, float* __restrict__ out, int grid)
{
    __shared__ double sred[MTHREADS/32][29];
    __shared__ double red[29];
    __shared__ double sGH[27];          // accepted GH (block0 only)
    __shared__ float  sRcur[9], stcur[3];
    __shared__ float  sstate[2];        // lam, lr
    __shared__ double sprev;

    const float fx = Kmat[0], cx = Kmat[2], fy = Kmat[4], cy = Kmat[5];
    const int lane = threadIdx.x & 31;
    const int wrp  = threadIdx.x >> 5;
    const float4* frf4 = (const float4*)fref;

    int kk = 0, ll = 0;
    if (lane >= 6 && lane < 27) { kk = c_hk[lane - 6]; ll = c_hl[lane - 6]; }

    const int wid = blockIdx.x * (MTHREADS/32) + wrp;
    const int nw  = grid * (MTHREADS/32);

    for (int step = 0; step <= NITERS; step++) {
        // ---- load pose to evaluate (init pose or candidate) ----
        float Rl[9], tl[3];
        if (step == 0) {
            #pragma unroll
            for (int i = 0; i < 9; i++) Rl[i] = R0[i];
            #pragma unroll
            for (int i = 0; i < 3; i++) tl[i] = t0[i];
        } else {
            #pragma unroll
            for (int i = 0; i < 9; i++) Rl[i] = g_Rc[i];
            #pragma unroll
            for (int i = 0; i < 3; i++) tl[i] = g_tc[i];
        }

        // ---- fused cost + grad/hess pass at this pose ----
        double acc = 0.0, acost = 0.0, acnt = 0.0;
        for (int i = wid; i < N_PTS; i += nw) {
            float X0 = pts[3*i], Y0 = pts[3*i+1], Z0 = pts[3*i+2];
            float X = Rl[0]*X0 + Rl[1]*Y0 + Rl[2]*Z0 + tl[0];
            float Y = Rl[3]*X0 + Rl[4]*Y0 + Rl[5]*Z0 + tl[1];
            float Z = Rl[6]*X0 + Rl[7]*Y0 + Rl[8]*Z0 + tl[2];
            float u = (fx*X + cx*Z) / Z;
            float v = (fy*Y + cy*Z) / Z;
            u = fminf(fmaxf(u, -1e6f), 1e6f);
            v = fminf(fmaxf(v, -1e6f), 1e6f);
            int px = (int)rintf(u) - 1;
            int py = (int)rintf(v) - 1;
            bool in = (px >= 0) && (py >= 0) && (px < IMW) && (py < IMH);
            if (!in) continue;   // warp-uniform (whole warp works on one point)

            const float4* pb = g_packed + (size_t)(py * WF + px) * 96;
            float4 f  = pb[lane];
            float4 a  = pb[32 + lane];
            float4 bb = pb[64 + lane];
            float4 fr = frf4[(size_t)i * 32 + lane];

            float ex = f.x - fr.x, ey = f.y - fr.y, ez = f.z - fr.z, ew = f.w - fr.w;
            acost += (double)(ex*ex + ey*ey + ez*ez + ew*ew);
            if (lane == 0) acnt += 1.0;

            float sxx = a.x*a.x + a.y*a.y + a.z*a.z + a.w*a.w;
            float syy = bb.x*bb.x + bb.y*bb.y + bb.z*bb.z + bb.w*bb.w;
            float sxy = a.x*bb.x + a.y*bb.y + a.z*bb.z + a.w*bb.w;
            float sxe = a.x*ex + a.y*ey + a.z*ez + a.w*ew;
            float sye = bb.x*ex + bb.y*ey + bb.z*ez + bb.w*ew;
            #pragma unroll
            for (int o = 16; o; o >>= 1) {
                sxx += __shfl_xor_sync(0xffffffffu, sxx, o);
                syy += __shfl_xor_sync(0xffffffffu, syy, o);
                sxy += __shfl_xor_sync(0xffffffffu, sxy, o);
                sxe += __shfl_xor_sync(0xffffffffu, sxe, o);
                sye += __shfl_xor_sync(0xffffffffu, sye, o);
            }

            float Zs  = (fabsf(Z) > 1e-6f) ? Z : 1e-6f;
            float iz  = 1.0f / Zs;
            float iz2 = iz * iz;
            float A00 =  fx * iz,              A01 = 0.0f,                 A02 = -fx * X * iz2;
            float A03 = -fx * X * Y * iz2,     A04 = fx*Z*iz + fx*X*X*iz2, A05 = -fx * Y * iz;
            float A10 = 0.0f,                  A11 = fy * iz,              A12 = -fy * Y * iz2;
            float A13 = -fy*Z*iz - fy*Y*Y*iz2, A14 = fy * X * Y * iz2,     A15 =  fy * X * iz;

            float a0 = (lane==0)?A00:(lane==1)?A01:(lane==2)?A02:(lane==3)?A03:(lane==4)?A04:A05;
            float a1 = (lane==0)?A10:(lane==1)?A11:(lane==2)?A12:(lane==3)?A13:(lane==4)?A14:A15;
            float A0k = __shfl_sync(0xffffffffu, a0, kk);
            float A0l = __shfl_sync(0xffffffffu, a0, ll);
            float A1k = __shfl_sync(0xffffffffu, a1, kk);
            float A1l = __shfl_sync(0xffffffffu, a1, ll);

            float term;
            if (lane < 6) term = sxe * a0 + sye * a1;
            else          term = sxx*A0k*A0l + sxy*(A0k*A1l + A1k*A0l) + syy*A1k*A1l;
            if (lane < 27) acc += (double)term;
        }

        // warp-reduce cost & count
        #pragma unroll
        for (int o = 16; o; o >>= 1) {
            acost += __shfl_xor_sync(0xffffffffu, acost, o);
            acnt  += __shfl_xor_sync(0xffffffffu, acnt,  o);
        }
        if (lane < 27) sred[wrp][lane] = acc;
        if (lane == 0) { sred[wrp][27] = acost; sred[wrp][28] = acnt; }
        __syncthreads();
        if (threadIdx.x < 29) {
            double s = 0.0;
            #pragma unroll
            for (int j = 0; j < MTHREADS/32; j++) s += sred[j][threadIdx.x];
            g_part[blockIdx.x][threadIdx.x] = s;
        }
        gbar(grid);

        // ---- block0: reduce partials, accept, solve next candidate ----
        if (blockIdx.x == 0) {
            for (int vv = wrp; vv < 29; vv += MTHREADS/32) {
                double s = 0.0;
                for (int b2 = lane; b2 < grid; b2 += 32) s += g_part[b2][vv];
                #pragma unroll
                for (int o = 16; o; o >>= 1) s += __shfl_xor_sync(0xffffffffu, s, o);
                if (lane == 0) red[vv] = s;
            }
            __syncthreads();
            if (threadIdx.x == 0) {
                double cost = 0.5 * red[27] / fmax(red[28], 1.0);
                if (step == 0) {
                    sprev = cost;
                    for (int i = 0; i < 27; i++) sGH[i] = red[i];
                    for (int i = 0; i < 9; i++) sRcur[i] = R0[i];
                    for (int i = 0; i < 3; i++) stcur[i] = t0[i];
                    sstate[0] = 0.01f; sstate[1] = 1.0f;
                } else {
                    bool accept = (cost <= sprev);
                    float lam = sstate[0] * (accept ? 0.1f : 10.0f);
                    sstate[0] = fminf(fmaxf(lam, 1e-6f), 1e4f);
                    sstate[1] = accept ? 1.0f : fminf(fmaxf(0.1f * sstate[1], 1e-3f), 1.0f);
                    if (accept) {
                        for (int i = 0; i < 27; i++) sGH[i] = red[i];
                        for (int i = 0; i < 9; i++) sRcur[i] = g_Rc[i];
                        for (int i = 0; i < 3; i++) stcur[i] = g_tc[i];
                        sprev = cost;
                    }
                }
                if (step < NITERS) {
                    solve_compose(sGH, sstate[0], sstate[1], sRcur, stcur);
                } else {
                    for (int i = 0; i < 9; i++) out[i] = sRcur[i];
                    for (int i = 0; i < 3; i++) out[9 + i] = stcur[i];
                }
            }
        }
        gbar(grid);
    }
}

// ---------------- launch ----------------
extern "C" void kernel_launch(void* const* d_in, const int* in_sizes, int n_in,
                              void* d_out, int out_size)
{
    const float* pts  = (const float*)d_in[0];   // pts3D (N,3)
    const float* fref = (const float*)d_in[1];   // feature_ref (N,C)
    const float* fm   = (const float*)d_in[2];   // feature_map_query (C,H,W)
    const float* gx   = (const float*)d_in[3];   // feature_grad_x
    const float* gy   = (const float*)d_in[4];   // feature_grad_y
    const float* Km   = (const float*)d_in[5];   // K (3,3)
    const float* R0   = (const float*)d_in[6];   // R_init
    const float* t0   = (const float*)d_in[7];   // t_init

    transpose_kernel<<<(HW / 32) * 3, 256>>>(fm, gx, gy);

    // Size the persistent grid to guaranteed co-residency (deadlock-safe barrier).
    int dev = 0;
    cudaGetDevice(&dev);
    int nsm = 148;
    cudaDeviceGetAttribute(&nsm, cudaDevAttrMultiProcessorCount, dev);
    int maxb = 0;
    cudaOccupancyMaxActiveBlocksPerMultiprocessor(&maxb, mega_kernel, MTHREADS, 0);
    if (maxb < 1) maxb = 1;
    int grid = nsm * maxb;
    if (grid > MAXB) grid = MAXB;

    mega_kernel<<<grid, MTHREADS>>>(pts, fref, Km, R0, t0, (float*)d_out, grid);
}

// round 5
// speedup vs baseline: 1.6252x; 1.1202x over previous
#include <cuda_runtime.h>
#include <math.h>

// Problem constants (fixed benchmark shapes)
#define N_PTS   50000
#define C_FEAT  128
#define HF      480
#define WF      640
#define IMW     640
#define IMH     480
#define HW      (HF*WF)
#define NITERS  10

#define MTHREADS 256
#define NWARP    (MTHREADS/32)
#define MAXB     1184

// ---------------- persistent device state ----------------
// Packed pixel-major maps: per pixel 96 float4 = [fm(32 f4) | gx(32 f4) | gy(32 f4)]
__device__ float4 g_packed[(size_t)HW * 96];

__device__ double   g_part[MAXB][29];   // per-block partials: 0..5 G, 6..26 H(ut), 27 sum(e2), 28 cnt
__device__ float    g_Rc[9], g_tc[3];   // candidate pose (block0 -> all blocks)
__device__ unsigned g_count = 0;        // barrier arrival counter (reset by releaser)
__device__ unsigned g_gen   = 0;        // barrier generation (monotonic)

// Hessian upper-triangle index maps (21 entries)
__device__ const int c_hk[21] = {0,0,0,0,0,0,1,1,1,1,1,2,2,2,2,3,3,3,4,4,5};
__device__ const int c_hl[21] = {0,1,2,3,4,5,1,2,3,4,5,2,3,4,5,3,4,5,4,5,5};

// ---------------- transpose (C,H,W) x3 -> (pix, map, C) ----------------
__global__ __launch_bounds__(256) void transpose_kernel(
    const float* __restrict__ fm, const float* __restrict__ gx, const float* __restrict__ gy)
{
    __shared__ float sh[32][C_FEAT + 1];
    int b    = blockIdx.x;            // (HW/32)*3 blocks
    int map  = b / (HW / 32);
    int tile = b % (HW / 32);
    int pix0 = tile * 32;
    const float* src = (map == 0) ? fm : (map == 1) ? gx : gy;

    int t = threadIdx.x, lane = t & 31, grp = t >> 5;   // 8 groups
    #pragma unroll
    for (int cb = 0; cb < C_FEAT; cb += 8) {
        int ch = cb + grp;
        sh[lane][ch] = src[(size_t)ch * HW + pix0 + lane];
    }
    __syncthreads();
    float* out = (float*)g_packed;
    #pragma unroll
    for (int pb = 0; pb < 32; pb += 8) {
        int p = pb + grp;
        size_t base = (size_t)(pix0 + p) * 384 + (size_t)map * 128;
        #pragma unroll
        for (int k = 0; k < 4; k++)
            out[base + k * 32 + lane] = sh[p][k * 32 + lane];
    }
}

// ---------------- software grid barrier ----------------
__device__ __forceinline__ void gbar(int grid) {
    __syncthreads();
    if (threadIdx.x == 0) {
        unsigned gen = *(volatile unsigned*)&g_gen;
        __threadfence();
        unsigned old = atomicAdd(&g_count, 1u);
        if (old == (unsigned)grid - 1u) {
            g_count = 0;
            __threadfence();
            atomicAdd(&g_gen, 1u);
        } else {
            while (*(volatile unsigned*)&g_gen == gen) { }
        }
        __threadfence();
    }
    __syncthreads();
}

// ---------------- 6x6 LM solve + pose composition (block0 thread0 only) ----------------
__device__ __noinline__ void solve_compose(
    const double* __restrict__ GH, float lam_f, float lr_f,
    const float* __restrict__ Rcur, const float* __restrict__ tcur)
{
    double G[6];
    for (int j = 0; j < 6; j++) G[j] = GH[j];
    double H[6][6];
    {
        int idx = 6;
        for (int k = 0; k < 6; k++)
            for (int l = k; l < 6; l++) { H[k][l] = GH[idx]; H[l][k] = GH[idx]; idx++; }
    }
    double lam = (double)lam_f;
    for (int k = 0; k < 6; k++) H[k][k] += lam * (H[k][k] + 1e-9);

    double M[6][7];
    for (int k = 0; k < 6; k++) { for (int j = 0; j < 6; j++) M[k][j] = H[k][j]; M[k][6] = G[k]; }
    for (int k = 0; k < 6; k++) {
        int p = k; double mx = fabs(M[k][k]);
        for (int r = k + 1; r < 6; r++) if (fabs(M[r][k]) > mx) { mx = fabs(M[r][k]); p = r; }
        if (p != k) for (int j = k; j < 7; j++) { double tmp = M[k][j]; M[k][j] = M[p][j]; M[p][j] = tmp; }
        double inv = 1.0 / M[k][k];
        for (int j = k; j < 7; j++) M[k][j] *= inv;
        for (int r = 0; r < 6; r++) if (r != k) {
            double f = M[r][k];
            for (int j = k; j < 7; j++) M[r][j] -= f * M[k][j];
        }
    }
    double lr = (double)lr_f;
    double dt0 = -lr * M[0][6], dt1 = -lr * M[1][6], dt2 = -lr * M[2][6];
    double w0  = -lr * M[3][6], w1  = -lr * M[4][6], w2  = -lr * M[5][6];

    double th2 = w0*w0 + w1*w1 + w2*w2;
    double th  = sqrt(th2 + 1e-24);
    double a, b;
    if (th < 1e-4) { a = 1.0 - th2 / 6.0; b = 0.5 - th2 / 24.0; }
    else           { a = sin(th) / th;    b = (1.0 - cos(th)) / (th2 + 1e-24); }
    double W[9]  = {0, -w2, w1,  w2, 0, -w0,  -w1, w0, 0};
    double W2[9];
    for (int r = 0; r < 3; r++)
        for (int c = 0; c < 3; c++) {
            double s = 0;
            for (int k = 0; k < 3; k++) s += W[r*3+k] * W[k*3+c];
            W2[r*3+c] = s;
        }
    double dr[9];
    for (int i = 0; i < 9; i++) dr[i] = a * W[i] + b * W2[i];
    dr[0] += 1.0; dr[4] += 1.0; dr[8] += 1.0;

    double Rc[9], tc[3];
    for (int r = 0; r < 3; r++)
        for (int c = 0; c < 3; c++) {
            double s = 0;
            for (int k = 0; k < 3; k++) s += dr[r*3+k] * (double)Rcur[k*3+c];
            Rc[r*3+c] = s;
        }
    for (int r = 0; r < 3; r++) {
        double s = 0;
        for (int k = 0; k < 3; k++) s += dr[r*3+k] * (double)tcur[k];
        tc[r] = s;
    }
    tc[0] += dt0; tc[1] += dt1; tc[2] += dt2;

    for (int i = 0; i < 9; i++) g_Rc[i] = (float)Rc[i];
    for (int i = 0; i < 3; i++) g_tc[i] = (float)tc[i];
}

// ---------------- persistent mega-kernel ----------------
__global__ __launch_bounds__(MTHREADS, 3)
void mega_kernel(const float* __restrict__ pts, const float* __restrict__ fref,
                 const float* __restrict__ Kmat, const float* __restrict__ R0,
                 const float* __restrict__ t0, float* __restrict__ out, int grid)
{
    __shared__ int    s_pix[MTHREADS];
    __shared__ float  s_X[MTHREADS], s_Y[MTHREADS], s_Z[MTHREADS];
    __shared__ int    s_idx[MTHREADS];
    __shared__ int    s_wcnt[NWARP];
    __shared__ double sred[NWARP][29];
    __shared__ double red[29];
    __shared__ double sGH[27];
    __shared__ float  sRcur[9], stcur[3];
    __shared__ float  sstate[2];        // lam, lr
    __shared__ double sprev;

    const float fx = Kmat[0], cx = Kmat[2], fy = Kmat[4], cy = Kmat[5];
    const int lane = threadIdx.x & 31;
    const int wrp  = threadIdx.x >> 5;
    const float4* frf4 = (const float4*)fref;

    int kk = 0, ll = 0;
    if (lane >= 6 && lane < 27) { kk = c_hk[lane - 6]; ll = c_hl[lane - 6]; }

    const int chunk = (N_PTS + grid - 1) / grid;
    const int base  = blockIdx.x * chunk;
    const int myn   = (base < N_PTS) ? min(chunk, N_PTS - base) : 0;

    for (int step = 0; step <= NITERS; step++) {
        const bool doGH = (step < NITERS);
        // ---- pose to evaluate ----
        float Rl[9], tl[3];
        if (step == 0) {
            #pragma unroll
            for (int i = 0; i < 9; i++) Rl[i] = R0[i];
            #pragma unroll
            for (int i = 0; i < 3; i++) tl[i] = t0[i];
        } else {
            #pragma unroll
            for (int i = 0; i < 9; i++) Rl[i] = g_Rc[i];
            #pragma unroll
            for (int i = 0; i < 3; i++) tl[i] = g_tc[i];
        }

        double acc = 0.0, acost = 0.0;
        int    validtot = 0;

        for (int tb = 0; tb < myn; tb += MTHREADS) {
            // ===== Phase A: thread-parallel projection + deterministic compaction =====
            int tloc = tb + threadIdx.x;
            bool valid = false;
            float X = 0.f, Y = 0.f, Z = 0.f;
            int pix = 0;
            if (tloc < myn) {
                int i = base + tloc;
                float X0 = pts[3*i], Y0 = pts[3*i+1], Z0 = pts[3*i+2];
                X = Rl[0]*X0 + Rl[1]*Y0 + Rl[2]*Z0 + tl[0];
                Y = Rl[3]*X0 + Rl[4]*Y0 + Rl[5]*Z0 + tl[1];
                Z = Rl[6]*X0 + Rl[7]*Y0 + Rl[8]*Z0 + tl[2];
                float u = (fx*X + cx*Z) / Z;
                float v = (fy*Y + cy*Z) / Z;
                u = fminf(fmaxf(u, -1e6f), 1e6f);
                v = fminf(fmaxf(v, -1e6f), 1e6f);
                int px = (int)rintf(u) - 1;
                int py = (int)rintf(v) - 1;
                valid = (px >= 0) && (py >= 0) && (px < IMW) && (py < IMH);
                pix = py * WF + px;
            }
            unsigned bal = __ballot_sync(0xffffffffu, valid);
            if (lane == 0) s_wcnt[wrp] = __popc(bal);
            __syncthreads();
            int off = 0, total = 0;
            #pragma unroll
            for (int w2 = 0; w2 < NWARP; w2++) {
                int c2 = s_wcnt[w2];
                if (w2 < wrp) off += c2;
                total += c2;
            }
            int pos = off + __popc(bal & ((1u << lane) - 1u));
            if (valid) {
                s_pix[pos] = pix; s_X[pos] = X; s_Y[pos] = Y; s_Z[pos] = Z;
                s_idx[pos] = base + tloc;
            }
            __syncthreads();
            validtot += total;

            // ===== Phase B: warps walk compacted list with 1-ahead prefetch =====
            int j = wrp;
            float4 f, a, bb, fr;
            if (j < total) {
                const float4* pb = g_packed + (size_t)s_pix[j] * 96;
                f  = pb[lane];
                fr = frf4[(size_t)s_idx[j] * 32 + lane];
                if (doGH) { a = pb[32 + lane]; bb = pb[64 + lane]; }
            }
            while (j < total) {
                int jn = j + NWARP;
                float4 fN, aN, bN, frN;
                if (jn < total) {
                    const float4* pn = g_packed + (size_t)s_pix[jn] * 96;
                    fN  = pn[lane];
                    frN = frf4[(size_t)s_idx[jn] * 32 + lane];
                    if (doGH) { aN = pn[32 + lane]; bN = pn[64 + lane]; }
                }

                float ex = f.x - fr.x, ey = f.y - fr.y, ez = f.z - fr.z, ew = f.w - fr.w;
                acost += (double)(ex*ex + ey*ey + ez*ez + ew*ew);

                if (doGH) {
                    float sxx = a.x*a.x + a.y*a.y + a.z*a.z + a.w*a.w;
                    float syy = bb.x*bb.x + bb.y*bb.y + bb.z*bb.z + bb.w*bb.w;
                    float sxy = a.x*bb.x + a.y*bb.y + a.z*bb.z + a.w*bb.w;
                    float sxe = a.x*ex + a.y*ey + a.z*ez + a.w*ew;
                    float sye = bb.x*ex + bb.y*ey + bb.z*ez + bb.w*ew;
                    #pragma unroll
                    for (int o = 16; o; o >>= 1) {
                        sxx += __shfl_xor_sync(0xffffffffu, sxx, o);
                        syy += __shfl_xor_sync(0xffffffffu, syy, o);
                        sxy += __shfl_xor_sync(0xffffffffu, sxy, o);
                        sxe += __shfl_xor_sync(0xffffffffu, sxe, o);
                        sye += __shfl_xor_sync(0xffffffffu, sye, o);
                    }

                    float Xp = s_X[j], Yp = s_Y[j], Zp = s_Z[j];
                    float Zs  = (fabsf(Zp) > 1e-6f) ? Zp : 1e-6f;
                    float iz  = 1.0f / Zs;
                    float iz2 = iz * iz;
                    float A00 =  fx * iz,                A01 = 0.0f,                   A02 = -fx * Xp * iz2;
                    float A03 = -fx * Xp * Yp * iz2,     A04 = fx*Zp*iz + fx*Xp*Xp*iz2, A05 = -fx * Yp * iz;
                    float A10 = 0.0f,                    A11 = fy * iz,                A12 = -fy * Yp * iz2;
                    float A13 = -fy*Zp*iz - fy*Yp*Yp*iz2, A14 = fy * Xp * Yp * iz2,    A15 =  fy * Xp * iz;

                    float a0 = (lane==0)?A00:(lane==1)?A01:(lane==2)?A02:(lane==3)?A03:(lane==4)?A04:A05;
                    float a1 = (lane==0)?A10:(lane==1)?A11:(lane==2)?A12:(lane==3)?A13:(lane==4)?A14:A15;
                    float A0k = __shfl_sync(0xffffffffu, a0, kk);
                    float A0l = __shfl_sync(0xffffffffu, a0, ll);
                    float A1k = __shfl_sync(0xffffffffu, a1, kk);
                    float A1l = __shfl_sync(0xffffffffu, a1, ll);

                    float term;
                    if (lane < 6) term = sxe * a0 + sye * a1;
                    else          term = sxx*A0k*A0l + sxy*(A0k*A1l + A1k*A0l) + syy*A1k*A1l;
                    if (lane < 27) acc += (double)term;
                }

                f = fN; a = aN; bb = bN; fr = frN;
                j = jn;
            }
            __syncthreads();   // protect smem before next tile's Phase A
        }

        // ---- block-level reduce & publish partials ----
        #pragma unroll
        for (int o = 16; o; o >>= 1)
            acost += __shfl_xor_sync(0xffffffffu, acost, o);
        if (lane < 27) sred[wrp][lane] = acc;
        if (lane == 0) sred[wrp][27] = acost;
        __syncthreads();
        if (threadIdx.x < 28) {
            double s = 0.0;
            #pragma unroll
            for (int jj = 0; jj < NWARP; jj++) s += sred[jj][threadIdx.x];
            g_part[blockIdx.x][threadIdx.x] = s;
        }
        if (threadIdx.x == 28) g_part[blockIdx.x][28] = (double)validtot;
        gbar(grid);

        // ---- block0: reduce partials, accept, next candidate ----
        if (blockIdx.x == 0) {
            for (int vv = wrp; vv < 29; vv += NWARP) {
                double s = 0.0;
                for (int b2 = lane; b2 < grid; b2 += 32) s += g_part[b2][vv];
                #pragma unroll
                for (int o = 16; o; o >>= 1) s += __shfl_xor_sync(0xffffffffu, s, o);
                if (lane == 0) red[vv] = s;
            }
            __syncthreads();
            if (threadIdx.x == 0) {
                double cost = 0.5 * red[27] / fmax(red[28], 1.0);
                if (step == 0) {
                    sprev = cost;
                    for (int i = 0; i < 27; i++) sGH[i] = red[i];
                    for (int i = 0; i < 9; i++) sRcur[i] = R0[i];
                    for (int i = 0; i < 3; i++) stcur[i] = t0[i];
                    sstate[0] = 0.01f; sstate[1] = 1.0f;
                } else {
                    bool accept = (cost <= sprev);
                    float lam = sstate[0] * (accept ? 0.1f : 10.0f);
                    sstate[0] = fminf(fmaxf(lam, 1e-6f), 1e4f);
                    sstate[1] = accept ? 1.0f : fminf(fmaxf(0.1f * sstate[1], 1e-3f), 1.0f);
                    if (accept) {
                        for (int i = 0; i < 27; i++) sGH[i] = red[i];
                        for (int i = 0; i < 9; i++) sRcur[i] = g_Rc[i];
                        for (int i = 0; i < 3; i++) stcur[i] = g_tc[i];
                        sprev = cost;
                    }
                }
                if (step < NITERS) {
                    solve_compose(sGH, sstate[0], sstate[1], sRcur, stcur);
                } else {
                    for (int i = 0; i < 9; i++) out[i] = sRcur[i];
                    for (int i = 0; i < 3; i++) out[9 + i] = stcur[i];
                }
            }
        }
        gbar(grid);
    }
}

// ---------------- launch ----------------
extern "C" void kernel_launch(void* const* d_in, const int* in_sizes, int n_in,
                              void* d_out, int out_size)
{
    const float* pts  = (const float*)d_in[0];   // pts3D (N,3)
    const float* fref = (const float*)d_in[1];   // feature_ref (N,C)
    const float* fm   = (const float*)d_in[2];   // feature_map_query (C,H,W)
    const float* gx   = (const float*)d_in[3];   // feature_grad_x
    const float* gy   = (const float*)d_in[4];   // feature_grad_y
    const float* Km   = (const float*)d_in[5];   // K (3,3)
    const float* R0   = (const float*)d_in[6];   // R_init
    const float* t0   = (const float*)d_in[7];   // t_init

    transpose_kernel<<<(HW / 32) * 3, 256>>>(fm, gx, gy);

    // Size the persistent grid to guaranteed co-residency (deadlock-safe barrier).
    int dev = 0;
    cudaGetDevice(&dev);
    int nsm = 148;
    cudaDeviceGetAttribute(&nsm, cudaDevAttrMultiProcessorCount, dev);
    int maxb = 0;
    cudaOccupancyMaxActiveBlocksPerMultiprocessor(&maxb, mega_kernel, MTHREADS, 0);
    if (maxb < 1) maxb = 1;
    int grid = nsm * maxb;
    if (grid > MAXB) grid = MAXB;

    mega_kernel<<<grid, MTHREADS>>>(pts, fref, Km, R0, t0, (float*)d_out, grid);
}